// round 17
// baseline (speedup 1.0000x reference)
#include <cuda_runtime.h>
#include <cuda_bf16.h>
#include <cstdint>
#include <cstddef>

// ---------------------------------------------------------------------------
// TaggingFNNDecoder: 2-layer LSTM tag decoder. B=32, T=256, D=1024, H=512, K=128
// Round 16: k_preH double-buffered cp.async pipeline (hide chunk load latency
// under MMA compute). Loop/setup/final = R15.
// ---------------------------------------------------------------------------

#define B_  32
#define T_  256
#define D_  1024
#define H_  512
#define K_  128
#define R_  2048    // 4*H gate rows
#define KC0 640     // cell0 reduced k-dim: h1(512) + e(128)
#define KC1 1024    // cell1 k-dim: h1(512) + h2(512)
#define G_  128     // persistent grid size (1 CTA/SM)
#define PS  34      // padded row stride for partial arrays (8B-aligned pairs)
#define LROW 128    // interleaved logits row stride (floats per tag)

// ------------------------- device scratch ----------------------------------
__device__ float d_pre0[(size_t)T_ * R_ * B_];   // 64 MB [t][row][b]
__device__ float d_W0[(size_t)R_ * KC0];         // [row][ W_hh0 | W_ih0[:,1024:] ]
__device__ float d_W1[(size_t)R_ * KC1];         // [row][ W_ih1 | W_hh1 ]
__device__ float d_bias1[R_];
__device__ float d_h1[2 * H_ * B_];              // double buffered [j][b]
__device__ float d_h2[2 * H_ * B_];
__device__ float d_c1[H_ * B_];
__device__ float d_c2[H_ * B_];
__device__ float d_logit0[K_ * LROW];            // interleaved initial logits
__device__ float d_logits[(size_t)T_ * K_ * LROW]; // interleaved raw logits

// bf16 split operands for the HMMA pre-projection GEMM
__device__ __nv_bfloat16 d_Ahi[(size_t)8192 * 1024];   // 16 MB
__device__ __nv_bfloat16 d_Alo[(size_t)8192 * 1024];   // 16 MB
__device__ __nv_bfloat16 d_Whi[(size_t)R_ * 1024];     // 4 MB
__device__ __nv_bfloat16 d_Wlo[(size_t)R_ * 1024];     // 4 MB

// central barrier counter (monotonic within one launch; reset by k_zero)
__device__ unsigned g_count;

// fast NaN-free activations
__device__ __forceinline__ float sigf(float x) {
    return __fdividef(1.0f, 1.0f + __expf(-x));
}
__device__ __forceinline__ float tanhfast(float x) {
    return 1.0f - __fdividef(2.0f, 1.0f + __expf(2.0f * x));
}

// packed fp32x2 helpers
__device__ __forceinline__ unsigned long long pk2(float x) {
    unsigned long long r; unsigned u = __float_as_uint(x);
    asm("mov.b64 %0, {%1, %1};" : "=l"(r) : "r"(u));
    return r;
}
__device__ __forceinline__ void fma2(unsigned long long& a,
                                     unsigned long long x, unsigned long long w) {
    asm("fma.rn.f32x2 %0, %1, %2, %0;" : "+l"(a) : "l"(x), "l"(w));
}
__device__ __forceinline__ void unpk2(float& lo, float& hi, unsigned long long v) {
    unsigned l, h;
    asm("mov.b64 {%0, %1}, %2;" : "=r"(l), "=r"(h) : "l"(v));
    lo = __uint_as_float(l); hi = __uint_as_float(h);
}

// split grid barrier
__device__ __forceinline__ void gbar_arrive() {
    __syncthreads();
    if (threadIdx.x == 0) {
        asm volatile("red.release.gpu.add.u32 [%0], %1;"
                     :: "l"(&g_count), "r"(1u) : "memory");
    }
}
__device__ __forceinline__ void gbar_wait(unsigned target) {
    if (threadIdx.x == 0) {
        unsigned v;
        do {
            asm volatile("ld.acquire.gpu.u32 %0, [%1];"
                         : "=r"(v) : "l"(&g_count) : "memory");
        } while ((int)(v - target) < 0);
    }
    __syncthreads();
}

// hybrid dot body (R9)
__device__ __forceinline__ void dot32(unsigned long long acc[4][2],
                                      const float* __restrict__ wbase,
                                      const float* __restrict__ xsrc,
                                      int r4, int b4) {
#pragma unroll 8
    for (int kk = 0; kk < 32; kk++) {
        float4 wv = *(const float4*)(wbase + kk * 16 + r4);
        unsigned long long x01, x23;
        asm("ld.global.cg.v2.b64 {%0,%1}, [%2];"
            : "=l"(x01), "=l"(x23) : "l"(xsrc + kk * 32 + b4));
        unsigned long long w0p = pk2(wv.x), w1p = pk2(wv.y);
        unsigned long long w2p = pk2(wv.z), w3p = pk2(wv.w);
        fma2(acc[0][0], x01, w0p); fma2(acc[0][1], x23, w0p);
        fma2(acc[1][0], x01, w1p); fma2(acc[1][1], x23, w1p);
        fma2(acc[2][0], x01, w2p); fma2(acc[2][1], x23, w2p);
        fma2(acc[3][0], x01, w3p); fma2(acc[3][1], x23, w3p);
    }
}

__device__ __forceinline__ void store_acc(float* part, int wbase_row,
                                          unsigned long long acc[4][2],
                                          int r4, int b4) {
#pragma unroll
    for (int rr = 0; rr < 4; rr++) {
        unsigned long long* p =
            (unsigned long long*)(part + (wbase_row + r4 + rr) * PS + b4);
        p[0] = acc[rr][0];
        p[1] = acc[rr][1];
    }
}

// -------------------- setup: pack weights + init states + bf16 split --------
__global__ void k_setup(const float* __restrict__ Wih0, const float* __restrict__ Whh0,
                        const float* __restrict__ Wih1, const float* __restrict__ Whh1,
                        const float* __restrict__ bih1, const float* __restrict__ bhh1,
                        const float* __restrict__ h_t,  const float* __restrict__ c_t,
                        const float* __restrict__ hid,  const float* __restrict__ W_out,
                        const float* __restrict__ b_out) {
    int row = blockIdx.x;          // 0..2047
    int tid = threadIdx.x;         // 256 threads
    // ---- weight pack (loop weights) ----
    const float4* s1 = (const float4*)(Whh0 + (size_t)row * H_);
    float4* dW0 = (float4*)(d_W0 + (size_t)row * KC0);
    for (int i = tid; i < H_ / 4; i += 256) dW0[i] = s1[i];
    const float4* s2 = (const float4*)(Wih0 + (size_t)row * (D_ + K_) + D_);
    for (int i = tid; i < K_ / 4; i += 256) dW0[H_ / 4 + i] = s2[i];
    float4* dW1 = (float4*)(d_W1 + (size_t)row * KC1);
    const float4* s3 = (const float4*)(Wih1 + (size_t)row * H_);
    const float4* s4 = (const float4*)(Whh1 + (size_t)row * H_);
    for (int i = tid; i < H_ / 4; i += 256) { dW1[i] = s3[i]; dW1[H_ / 4 + i] = s4[i]; }
    if (tid == 0) d_bias1[row] = bih1[row] + bhh1[row];

    // ---- bf16 split of W_ih0[:, :1024] (GEMM B operand) ----
    for (int k = tid; k < 1024; k += 256) {
        float v = Wih0[(size_t)row * (D_ + K_) + k];
        __nv_bfloat16 hv = __float2bfloat16(v);
        d_Whi[(size_t)row * 1024 + k] = hv;
        d_Wlo[(size_t)row * 1024 + k] = __float2bfloat16(v - __bfloat162float(hv));
    }
    // ---- bf16 split of hiddens (GEMM A operand); 4096 elems per block ----
    {
        size_t base = (size_t)row * 4096;
        for (int i = tid; i < 4096; i += 256) {
            float v = hid[base + i];
            __nv_bfloat16 hv = __float2bfloat16(v);
            d_Ahi[base + i] = hv;
            d_Alo[base + i] = __float2bfloat16(v - __bfloat162float(hv));
        }
    }

    // ---- logits prefill with output bias (blocks 0..255 <-> t), float4 ----
    if (row < 256) {
        float4* dst = (float4*)(d_logits + (size_t)row * K_ * LROW);
        for (int i = tid; i < K_ * LROW / 4; i += 256) {
            float bv = b_out[i >> 5];
            dst[i] = make_float4(bv, bv, bv, bv);
        }
    }
    // ---- state transpose (blocks 0..63) ----
    if (row < 64) {
        int idx = row * 256 + tid;                 // 0..16383 = j*32+b
        int j = idx >> 5, b = idx & 31;
        d_h1[idx] = h_t[b * H_ + j];
        d_h2[idx] = h_t[B_ * H_ + b * H_ + j];
        d_c1[idx] = c_t[b * H_ + j];
        d_c2[idx] = c_t[B_ * H_ + b * H_ + j];
    }
    // ---- initial tag logits (blocks 64..95, threads 0..127) ----
    if (row >= 64 && row < 96 && tid < 128) {
        int b = row - 64;
        int k = tid;
        const float* x  = hid + (size_t)b * T_ * D_;
        const float* wr = W_out + (size_t)k * H_;
        float a0 = 0.f, a1 = 0.f, a2 = 0.f, a3 = 0.f;
        for (int j = 0; j < H_; j += 4) {
            float4 w4 = *(const float4*)(wr + j);
            a0 += w4.x * x[j + 0];
            a1 += w4.y * x[j + 1];
            a2 += w4.z * x[j + 2];
            a3 += w4.w * x[j + 3];
        }
        d_logit0[k * LROW + ((b & 3) << 5) + (b >> 2)] =
            (a0 + a1) + (a2 + a3) + b_out[k];
    }
}

// reset barrier counter
__global__ void k_zero() {
    if (threadIdx.x == 0) g_count = 0;
}

// ----------------------- mma.sync k_pre helpers ------------------------------
#define SMEM_SWZ(off) ((off) ^ (((off) >> 3) & 0x70))

__device__ __forceinline__ uint32_t smem_u32(const void* p) {
    uint32_t a;
    asm("{ .reg .u64 t; cvta.to.shared.u64 t, %1; cvt.u32.u64 %0, t; }"
        : "=r"(a) : "l"(p));
    return a;
}
__device__ __forceinline__ void cpasync16(uint32_t dst, const void* src) {
    asm volatile("cp.async.ca.shared.global [%0], [%1], 16;"
                 :: "r"(dst), "l"(src) : "memory");
}
__device__ __forceinline__ void lda4(uint32_t a[4], uint32_t addr) {
    asm volatile("ldmatrix.sync.aligned.m8n8.x4.shared.b16 {%0,%1,%2,%3}, [%4];"
                 : "=r"(a[0]), "=r"(a[1]), "=r"(a[2]), "=r"(a[3]) : "r"(addr));
}
__device__ __forceinline__ void ldb2(uint32_t b[2], uint32_t addr) {
    asm volatile("ldmatrix.sync.aligned.m8n8.x2.shared.b16 {%0,%1}, [%2];"
                 : "=r"(b[0]), "=r"(b[1]) : "r"(addr));
}
__device__ __forceinline__ void mma16816(float c[4], const uint32_t a[4],
                                         const uint32_t b[2]) {
    asm volatile(
        "mma.sync.aligned.m16n8k16.row.col.f32.bf16.bf16.f32 "
        "{%0,%1,%2,%3}, {%4,%5,%6,%7}, {%8,%9}, {%0,%1,%2,%3};"
        : "+f"(c[0]), "+f"(c[1]), "+f"(c[2]), "+f"(c[3])
        : "r"(a[0]), "r"(a[1]), "r"(a[2]), "r"(a[3]), "r"(b[0]), "r"(b[1]));
}

// -------- pre-projection GEMM: C[8192m x 2048n] = A x W^T, bf16-split-3 -----
// 2-stage double-buffered cp.async pipeline. Two launches (n_base = 0, 16).
// Per-stage SMEM: Ahi 16K | Alo 16K | Bhi 8K | Blo 8K = 48K; 2 stages = 96K.
#define STG_SZ   49152
#define SMP_AHI  0
#define SMP_ALO  16384
#define SMP_BHI  32768
#define SMP_BLO  40960
#define SMP_TOTAL (2 * STG_SZ)
__global__ void __launch_bounds__(256) k_preH(const float* __restrict__ bih,
                                              const float* __restrict__ bhh,
                                              int n_base) {
    extern __shared__ char smem[];
    uint32_t sb = smem_u32(smem);
    int tid = threadIdx.x;
    int lane = tid & 31, w = tid >> 5;
    int n0 = (n_base + blockIdx.x) * 64;
    int m0 = blockIdx.y * 128;
    int wmbase = (w >> 1) * 32;    // 0,32,64,96
    int wnbase = (w & 1) * 32;     // 0,32

    int am = tid >> 1, ah = tid & 1;
    int aRowL = lane & 15;
    int aKL   = lane >> 4;
    int bRowL = lane & 7;
    int bKL   = (lane >> 3) & 1;
    int rowB2 = tid >> 2, gB = (tid & 3) * 2;

    // staging source base pointers
    const __nv_bfloat16* gha0 = d_Ahi + (size_t)(m0 + am) * 1024 + ah * 32;
    const __nv_bfloat16* gla0 = d_Alo + (size_t)(m0 + am) * 1024 + ah * 32;
    const __nv_bfloat16* ghb0 = d_Whi + (size_t)(n0 + rowB2) * 1024 + gB * 8;
    const __nv_bfloat16* glb0 = d_Wlo + (size_t)(n0 + rowB2) * 1024 + gB * 8;
    // staging dst offsets (within a stage)
    uint32_t offA[4], offB[2];
#pragma unroll
    for (int g = 0; g < 4; g++)
        offA[g] = SMEM_SWZ((uint32_t)(am * 128 + (ah * 4 + g) * 16));
#pragma unroll
    for (int g = 0; g < 2; g++)
        offB[g] = SMEM_SWZ((uint32_t)(rowB2 * 128 + (gB + g) * 16));

#define STAGE(kc, buf) do {                                                    \
    uint32_t base = sb + (buf) * STG_SZ;                                       \
    const __nv_bfloat16* _ga = gha0 + (kc) * 64;                               \
    const __nv_bfloat16* _la = gla0 + (kc) * 64;                               \
    _Pragma("unroll")                                                          \
    for (int g = 0; g < 4; g++) {                                              \
        cpasync16(base + SMP_AHI + offA[g], _ga + g * 8);                      \
        cpasync16(base + SMP_ALO + offA[g], _la + g * 8);                      \
    }                                                                          \
    const __nv_bfloat16* _gb = ghb0 + (kc) * 64;                               \
    const __nv_bfloat16* _lb = glb0 + (kc) * 64;                               \
    _Pragma("unroll")                                                          \
    for (int g = 0; g < 2; g++) {                                              \
        cpasync16(base + SMP_BHI + offB[g], _gb + g * 8);                      \
        cpasync16(base + SMP_BLO + offB[g], _lb + g * 8);                      \
    }                                                                          \
    asm volatile("cp.async.commit_group;" ::: "memory");                       \
} while (0)

    float c[2][4][4];
#pragma unroll
    for (int mt = 0; mt < 2; mt++)
#pragma unroll
        for (int nt = 0; nt < 4; nt++)
#pragma unroll
            for (int i = 0; i < 4; i++) c[mt][nt][i] = 0.f;

    STAGE(0, 0);

    for (int kc = 0; kc < 16; kc++) {
        int buf = kc & 1;
        if (kc < 15) {
            STAGE(kc + 1, buf ^ 1);
            asm volatile("cp.async.wait_group 1;" ::: "memory");
        } else {
            asm volatile("cp.async.wait_group 0;" ::: "memory");
        }
        __syncthreads();

        uint32_t basek = sb + buf * STG_SZ;
#pragma unroll
        for (int ks = 0; ks < 4; ks++) {
            uint32_t aHi[2][4], aLo[2][4];
#pragma unroll
            for (int mt = 0; mt < 2; mt++) {
                int row = wmbase + mt * 16 + aRowL;
                uint32_t off = (uint32_t)(row * 128
                              + (((ks * 2 + aKL) * 16) ^ ((row & 7) << 4)));
                lda4(aHi[mt], basek + SMP_AHI + off);
                lda4(aLo[mt], basek + SMP_ALO + off);
            }
#pragma unroll
            for (int nt = 0; nt < 4; nt++) {
                uint32_t bHi[2], bLo[2];
                int row = wnbase + nt * 8 + bRowL;
                uint32_t off = (uint32_t)(row * 128
                              + (((ks * 2 + bKL) * 16) ^ ((row & 7) << 4)));
                ldb2(bHi, basek + SMP_BHI + off);
                ldb2(bLo, basek + SMP_BLO + off);
#pragma unroll
                for (int mt = 0; mt < 2; mt++) {
                    mma16816(c[mt][nt], aHi[mt], bHi);
                    mma16816(c[mt][nt], aHi[mt], bLo);
                    mma16816(c[mt][nt], aLo[mt], bHi);
                }
            }
        }
        __syncthreads();
    }

#pragma unroll
    for (int mt = 0; mt < 2; mt++) {
        int m = m0 + wmbase + mt * 16 + (lane >> 2);
        int tt = m & 255, bb = m >> 8;
        int tt8 = (m + 8) & 255;
#pragma unroll
        for (int nt = 0; nt < 4; nt++) {
            int nc = n0 + wnbase + nt * 8 + 2 * (lane & 3);
            float bz0 = bih[nc] + bhh[nc];
            float bz1 = bih[nc + 1] + bhh[nc + 1];
            d_pre0[((size_t)tt  * R_ + nc)     * B_ + bb] = c[mt][nt][0] + bz0;
            d_pre0[((size_t)tt  * R_ + nc + 1) * B_ + bb] = c[mt][nt][1] + bz1;
            d_pre0[((size_t)tt8 * R_ + nc)     * B_ + bb] = c[mt][nt][2] + bz0;
            d_pre0[((size_t)tt8 * R_ + nc + 1) * B_ + bb] = c[mt][nt][3] + bz1;
        }
    }
}

// ------------------------- persistent recurrence (R15) -----------------------
__global__ void __launch_bounds__(512, 1) k_loop(const float* __restrict__ W_out,
                                                 const float* __restrict__ b_out) {
    extern __shared__ float smemf[];
    float* w0s     = smemf;
    float* w1s     = w0s + KC0 * 16;
    float* woutT   = w1s + KC1 * 16;
    float* bias1s  = woutT + 512;
    float* parthA  = bias1s + 32;
    float* partB   = parthA + 256 * PS;
    float* zps     = partB + 256 * PS;
    float* rowHA   = zps + 512;
    float* rowH    = rowHA + 16 * PS;
    float* rowE    = rowH + 16 * PS;
    float* zs      = rowE + 16 * PS;
    float* h2s     = zs + 32;

    const int c    = blockIdx.x;
    const int tid  = threadIdx.x;
    const int lane = tid & 31;
    const int w    = tid >> 5;
    const int r_   = tid >> 5;
    const int r4   = (lane >> 3) << 2;
    const int b4   = (lane & 7) << 2;
    const int bo   = ((lane & 3) << 5) + (lane >> 2);

#pragma unroll
    for (int r = 0; r < 16; r++) {
        int grow = (r >> 2) * H_ + c * 4 + (r & 3);
        const float* src0 = d_W0 + (size_t)grow * KC0;
        for (int k = tid; k < KC0; k += 512) w0s[k * 16 + r] = src0[k];
        const float* src1 = d_W1 + (size_t)grow * KC1;
        for (int k = tid; k < KC1; k += 512) w1s[k * 16 + r] = src1[k];
        if (tid == 0) bias1s[r] = d_bias1[grow];
    }
    {
        int ul2 = tid >> 7, k2 = tid & 127;
        woutT[tid] = W_out[(size_t)k2 * H_ + c * 4 + ul2];
    }
    __syncthreads();

    float c1_reg = 0.f, c2_reg = 0.f;
    int b = tid & 31, ul = tid >> 5;
    int u = c * 4 + (ul & 3);
    float pre[4];
    if (tid < 128) {
        c1_reg = d_c1[u * 32 + b];
        c2_reg = d_c2[u * 32 + b];
#pragma unroll
        for (int g = 0; g < 4; g++)
            pre[g] = __ldcg(&d_pre0[((size_t)0 * R_ + g * H_ + u) * B_ + b]);
    }

    {
        unsigned long long acc[4][2];
#pragma unroll
        for (int i = 0; i < 4; i++) { acc[i][0] = 0ull; acc[i][1] = 0ull; }
        dot32(acc, w0s + (w * 32) * 16, d_h1 + (w * 32) * 32, r4, b4);
        store_acc(parthA, w * 16, acc, r4, b4);
    }
    __syncthreads();
    {
        float sh = 0.f;
#pragma unroll
        for (int w2 = 0; w2 < 16; w2++) sh += parthA[(w2 * 16 + r_) * PS + lane];
        rowHA[r_ * PS + lane] = sh;
    }
    __syncthreads();

    unsigned tgt = G_;

    for (int t = 0; t < T_; t++) {
        const int old = t & 1, nw = old ^ 1;
        float*       __restrict__ h1new = d_h1 + nw  * (H_ * B_);
        const float* __restrict__ h2old = d_h2 + old * (H_ * B_);
        float*       __restrict__ h2new = d_h2 + nw  * (H_ * B_);

        {
            unsigned long long acce[8];
#pragma unroll
            for (int p = 0; p < 8; p++) acce[p] = 0ull;
            const float* lg = (t == 0) ? d_logit0
                                       : d_logits + (size_t)(t - 1) * (K_ * LROW);
            int ke0 = w * 8;
            float lv[8];
#pragma unroll
            for (int kk = 0; kk < 8; kk++)
                lv[kk] = __ldcg(lg + (ke0 + kk) * LROW + bo);
            float zp = 0.f;
#pragma unroll
            for (int kk = 0; kk < 8; kk++) {
                float ev = __expf(lv[kk]);
                zp += ev;
                unsigned long long xx = pk2(ev);
                const ulonglong2* q = (const ulonglong2*)(w0s + (H_ + ke0 + kk) * 16);
                ulonglong2 q0 = q[0], q1 = q[1], q2 = q[2], q3 = q[3];
                fma2(acce[0], xx, q0.x); fma2(acce[1], xx, q0.y);
                fma2(acce[2], xx, q1.x); fma2(acce[3], xx, q1.y);
                fma2(acce[4], xx, q2.x); fma2(acce[5], xx, q2.y);
                fma2(acce[6], xx, q3.x); fma2(acce[7], xx, q3.y);
            }
            zps[w * 32 + lane] = zp;
#pragma unroll
            for (int p = 0; p < 8; p++) {
                float lo, hi; unpk2(lo, hi, acce[p]);
                partB[(w * 16 + 2 * p + 0) * PS + lane] = lo;
                partB[(w * 16 + 2 * p + 1) * PS + lane] = hi;
            }
        }
        __syncthreads();

        {
            float se = 0.f;
#pragma unroll
            for (int w2 = 0; w2 < 16; w2++) se += partB[(w2 * 16 + r_) * PS + lane];
            rowE[r_ * PS + lane] = se;
            if (tid < 32) {
                float z = 0.f;
#pragma unroll
                for (int w2 = 0; w2 < 16; w2++) z += zps[w2 * 32 + tid];
                zs[tid] = z;
            }
        }
        __syncthreads();

        if (tid < 128) {
            float invZ = __fdividef(1.0f, zs[b]);
            float gate[4];
#pragma unroll
            for (int g = 0; g < 4; g++) {
                int r = g * 4 + ul;
                gate[g] = pre[g] + rowHA[r * PS + b] + rowE[r * PS + b] * invZ;
            }
            float iv = sigf(gate[0]);
            float fv = sigf(gate[1]);
            float gv = tanhfast(gate[2]);
            float ov = sigf(gate[3]);
            c1_reg = fv * c1_reg + iv * gv;
            h1new[u * 32 + b] = ov * tanhfast(c1_reg);
        }
        gbar_arrive();

        unsigned long long acc1[4][2];
#pragma unroll
        for (int i = 0; i < 4; i++) { acc1[i][0] = 0ull; acc1[i][1] = 0ull; }
        dot32(acc1, w1s + (H_ + w * 32) * 16, h2old + (w * 32) * 32, r4, b4);
        gbar_wait(tgt); tgt += G_;

        dot32(acc1, w1s + (w * 32) * 16, h1new + (w * 32) * 32, r4, b4);
        store_acc(partB, w * 16, acc1, r4, b4);
        __syncthreads();

        {
            float s = 0.f;
#pragma unroll
            for (int w2 = 0; w2 < 16; w2++) s += partB[(w2 * 16 + r_) * PS + lane];
            rowH[r_ * PS + lane] = s;
        }
        __syncthreads();

        if (tid < 128) {
            float gate[4];
#pragma unroll
            for (int g = 0; g < 4; g++) {
                int r = g * 4 + ul;
                gate[g] = bias1s[r] + rowH[r * PS + b];
            }
            float iv = sigf(gate[0]);
            float fv = sigf(gate[1]);
            float gv = tanhfast(gate[2]);
            float ov = sigf(gate[3]);
            c2_reg = fv * c2_reg + iv * gv;
            float h2v = ov * tanhfast(c2_reg);
            h2new[u * 32 + b] = h2v;
            h2s[(ul & 3) * 32 + b] = h2v;
        }
        __syncthreads();

        {
            float h0 = h2s[lane];
            float h1v = h2s[32 + lane];
            float h2q = h2s[64 + lane];
            float h3 = h2s[96 + lane];
            float* dstl = d_logits + (size_t)t * (K_ * LROW);
            int k0 = w * 8;
#pragma unroll
            for (int kk = 0; kk < 8; kk++) {
                int kq = k0 + kk;
                float v = woutT[kq] * h0 + woutT[128 + kq] * h1v
                        + woutT[256 + kq] * h2q + woutT[384 + kq] * h3;
                atomicAdd(dstl + kq * LROW + bo, v);
            }
        }
        if (tid < 128) {
            int tn = (t + 1 < T_) ? (t + 1) : t;
#pragma unroll
            for (int g = 0; g < 4; g++)
                pre[g] = __ldcg(&d_pre0[((size_t)tn * R_ + g * H_ + u) * B_ + b]);
        }
        gbar_arrive();

        {
            unsigned long long acc[4][2];
#pragma unroll
            for (int i = 0; i < 4; i++) { acc[i][0] = 0ull; acc[i][1] = 0ull; }
            dot32(acc, w0s + (w * 32) * 16, h1new + (w * 32) * 32, r4, b4);
            store_acc(parthA, w * 16, acc, r4, b4);
        }
        __syncthreads();
        {
            float sh = 0.f;
#pragma unroll
            for (int w2 = 0; w2 < 16; w2++) sh += parthA[(w2 * 16 + r_) * PS + lane];
            rowHA[r_ * PS + lane] = sh;
        }
        gbar_wait(tgt); tgt += G_;
    }
}

// --------------------------- final masked softmax ----------------------------
__global__ void __launch_bounds__(256) k_final(const float* __restrict__ mask,
                                               float* __restrict__ out) {
    int tid = threadIdx.x, lane = tid & 31, w = tid >> 5;
    int gidx = blockIdx.x * 8 + w;
    int b = gidx >> 8, t = gidx & 255;
    float pen = (1.0f - mask[b * T_ + t]) * -1e32f;
    int bo = ((b & 3) << 5) + (b >> 2);
    float v[4];
#pragma unroll
    for (int i = 0; i < 4; i++)
        v[i] = d_logits[(size_t)t * (K_ * LROW) + (lane + 32 * i) * LROW + bo] + pen;
    float mx = fmaxf(fmaxf(v[0], v[1]), fmaxf(v[2], v[3]));
#pragma unroll
    for (int o = 16; o > 0; o >>= 1) mx = fmaxf(mx, __shfl_xor_sync(~0u, mx, o));
    float s = 0.f;
#pragma unroll
    for (int i = 0; i < 4; i++) { v[i] = __expf(v[i] - mx); s += v[i]; }
#pragma unroll
    for (int o = 16; o > 0; o >>= 1) s += __shfl_xor_sync(~0u, s, o);
    float inv = 1.0f / s;
#pragma unroll
    for (int i = 0; i < 4; i++)
        out[((size_t)b * T_ + t) * K_ + lane + 32 * i] = v[i] * inv;
}

// ----------------------------------------------------------------------------
extern "C" void kernel_launch(void* const* d_in, const int* in_sizes, int n_in,
                              void* d_out, int out_size) {
    const float* hiddens = (const float*)d_in[0];
    const float* h_t     = (const float*)d_in[1];
    const float* c_t     = (const float*)d_in[2];
    const float* mask    = (const float*)d_in[3];
    const float* W_out   = (const float*)d_in[4];
    const float* b_out   = (const float*)d_in[5];
    const float* W_ih0   = (const float*)d_in[6];
    const float* W_hh0   = (const float*)d_in[7];
    const float* b_ih0   = (const float*)d_in[8];
    const float* b_hh0   = (const float*)d_in[9];
    const float* W_ih1   = (const float*)d_in[10];
    const float* W_hh1   = (const float*)d_in[11];
    const float* b_ih1   = (const float*)d_in[12];
    const float* b_hh1   = (const float*)d_in[13];
    float* out = (float*)d_out;

    const int SMEM_LOOP = 46880 * 4;   // same as R14
    cudaFuncSetAttribute(k_loop, cudaFuncAttributeMaxDynamicSharedMemorySize, SMEM_LOOP);
    cudaFuncSetAttribute(k_preH, cudaFuncAttributeMaxDynamicSharedMemorySize, SMP_TOTAL);

    // order: slot 4 (ncu capture) = k_preH(half 2)
    k_setup<<<R_, 256>>>(W_ih0, W_hh0, W_ih1, W_hh1, b_ih1, b_hh1,
                         h_t, c_t, hiddens, W_out, b_out);
    k_zero<<<1, 32>>>();
    k_preH<<<dim3(16, 64), 256, SMP_TOTAL>>>(b_ih0, b_hh0, 0);
    k_preH<<<dim3(16, 64), 256, SMP_TOTAL>>>(b_ih0, b_hh0, 16);
    k_loop<<<G_, 512, SMEM_LOOP>>>(W_out, b_out);
    k_final<<<1024, 256>>>(mask, out);
}